// round 3
// baseline (speedup 1.0000x reference)
#include <cuda_runtime.h>
#include <cstdint>

// Max-unpool 2x2 (kernel=stride=2, non-overlapping).
// x:     [N, C, H, W]   fp32
// where: [N, C, H, W]   int32 in {0..3}
// out:   [N, C, 2H, 2W] fp32
//
// R3: same dense-store layout as R2 (one thread-unit = 2 input pixels ->
// one float4 per output row; warp stores are fully dense 512B blocks).
// Changes: ILP=2 (each thread handles two units from disjoint halves of the
// problem -> 4 independent LDGs in flight), streaming cache hints
// (__ldcs / __stcs: data is never re-touched), 512-thread blocks.

static constexpr int N = 32, C = 64, H = 64, W = 64;
static constexpr int W2 = W / 2;          // 2-pixel units per input row = 32
static constexpr int OW = 2 * W;          // output width = 128
static constexpr int ROWS = N * C * H;
static constexpr int TOTAL = ROWS * W2;   // total units = 4,194,304
static constexpr int HALF  = TOTAL / 2;

__device__ __forceinline__ void do_unit(int idx,
                                        const float2* __restrict__ x2,
                                        const int2* __restrict__ w2,
                                        float* __restrict__ out)
{
    int qw  = idx & (W2 - 1);
    int row = idx >> 5;
    int h   = row & (H - 1);
    int nc  = row >> 6;

    float2 xv = __ldcs(&x2[idx]);
    int2   wv = __ldcs(&w2[idx]);

    float4 top, bot;
    top.x = (wv.x == 0) ? xv.x : 0.f;
    top.y = (wv.x == 1) ? xv.x : 0.f;
    top.z = (wv.y == 0) ? xv.y : 0.f;
    top.w = (wv.y == 1) ? xv.y : 0.f;

    bot.x = (wv.x == 2) ? xv.x : 0.f;
    bot.y = (wv.x == 3) ? xv.x : 0.f;
    bot.z = (wv.y == 2) ? xv.y : 0.f;
    bot.w = (wv.y == 3) ? xv.y : 0.f;

    size_t obase = (size_t)nc * (2 * H * OW) + (size_t)(2 * h) * OW + (size_t)qw * 4;
    __stcs(reinterpret_cast<float4*>(out + obase),      top);
    __stcs(reinterpret_cast<float4*>(out + obase + OW), bot);
}

__global__ __launch_bounds__(512)
void unpool2x2_kernel(const float2* __restrict__ x2,
                      const int2* __restrict__ w2,
                      float* __restrict__ out)
{
    int t = blockIdx.x * blockDim.x + threadIdx.x;     // 0 .. HALF-1
    if (t >= HALF) return;
    // Two independent units from disjoint halves: loads for both can be in
    // flight simultaneously (MLP=4 per thread).
    do_unit(t,        x2, w2, out);
    do_unit(t + HALF, x2, w2, out);
}

extern "C" void kernel_launch(void* const* d_in, const int* in_sizes, int n_in,
                              void* d_out, int out_size)
{
    const float2* x2 = (const float2*)d_in[0];
    const int2*   w2 = (const int2*)d_in[1];
    float* out = (float*)d_out;

    int threads = 512;
    int blocks = (HALF + threads - 1) / threads;   // 4096
    unpool2x2_kernel<<<blocks, threads>>>(x2, w2, out);
}

// round 4
// speedup vs baseline: 1.0163x; 1.0163x over previous
#include <cuda_runtime.h>
#include <cstdint>

// Max-unpool 2x2 (kernel=stride=2, non-overlapping).
// x:     [N, C, H, W]   fp32
// where: [N, C, H, W]   int32 in {0..3}
// out:   [N, C, 2H, 2W] fp32
//
// R4 = R2 layout (optimal: fully dense, fully sequential read and write
// streams; one thread = 2 input pixels = one float4 per output row),
// with streaming cache policy as the single isolated change:
//   __ldcg loads  (L2-only, no L1 allocation -- inputs never re-read)
//   __stcs stores (evict-first -- output never re-touched)

static constexpr int N = 32, C = 64, H = 64, W = 64;
static constexpr int W2 = W / 2;          // 2-pixel units per input row = 32
static constexpr int OW = 2 * W;          // output width = 128
static constexpr int ROWS = N * C * H;
static constexpr int TOTAL = ROWS * W2;   // 4,194,304 threads

__global__ __launch_bounds__(256)
void unpool2x2_kernel(const float2* __restrict__ x2,
                      const int2* __restrict__ w2,
                      float* __restrict__ out)
{
    int idx = blockIdx.x * blockDim.x + threadIdx.x;
    if (idx >= TOTAL) return;

    int qw  = idx & (W2 - 1);      // unit within row
    int row = idx >> 5;            // (n,c,h)
    int h   = row & (H - 1);
    int nc  = row >> 6;

    float2 xv = __ldcg(&x2[idx]);
    int2   wv = __ldcg(&w2[idx]);

    // pixel 0 -> cols 0,1 of the 4-span; pixel 1 -> cols 2,3
    float4 top, bot;
    top.x = (wv.x == 0) ? xv.x : 0.f;
    top.y = (wv.x == 1) ? xv.x : 0.f;
    top.z = (wv.y == 0) ? xv.y : 0.f;
    top.w = (wv.y == 1) ? xv.y : 0.f;

    bot.x = (wv.x == 2) ? xv.x : 0.f;
    bot.y = (wv.x == 3) ? xv.x : 0.f;
    bot.z = (wv.y == 2) ? xv.y : 0.f;
    bot.w = (wv.y == 3) ? xv.y : 0.f;

    size_t obase = (size_t)nc * (2 * H * OW) + (size_t)(2 * h) * OW + (size_t)qw * 4;
    __stcs(reinterpret_cast<float4*>(out + obase),      top);
    __stcs(reinterpret_cast<float4*>(out + obase + OW), bot);
}

extern "C" void kernel_launch(void* const* d_in, const int* in_sizes, int n_in,
                              void* d_out, int out_size)
{
    const float2* x2 = (const float2*)d_in[0];
    const int2*   w2 = (const int2*)d_in[1];
    float* out = (float*)d_out;

    int threads = 256;
    int blocks = (TOTAL + threads - 1) / threads;   // 16384
    unpool2x2_kernel<<<blocks, threads>>>(x2, w2, out);
}